// round 3
// baseline (speedup 1.0000x reference)
#include <cuda_runtime.h>

typedef unsigned long long ull;

// ---- packed f32x2 helpers (Blackwell FFMA2 path: only reachable via PTX) ----
__device__ __forceinline__ ull pk(float lo, float hi){
  ull r; asm("mov.b64 %0, {%1, %2};" : "=l"(r) : "f"(lo), "f"(hi)); return r;
}
__device__ __forceinline__ float2 upk(ull v){
  float2 r; asm("mov.b64 {%0, %1}, %2;" : "=f"(r.x), "=f"(r.y) : "l"(v)); return r;
}
__device__ __forceinline__ ull f2fma(ull a, ull b, ull c){
  ull d; asm("fma.rn.f32x2 %0, %1, %2, %3;" : "=l"(d) : "l"(a), "l"(b), "l"(c)); return d;
}

namespace cv {
constexpr int B = 4, C = 128, H = 128, W = 256, D = 81;
constexpr int HT = 2;      // output rows per block
constexpr int WT = 64;     // output cols per block
constexpr int XR = 10;     // x2 halo rows (HT + 8)
constexpr int XCU = 72;    // x2 halo cols used (WT + 8)
constexpr int XC = 80;     // padded stride
constexpr int NT = 288;    // 16 w-groups * 2 h * 9 i  (one warp per i-value)
constexpr int PIPE = 4;
constexpr int HW = H * W;
constexpr int X2ELEMS = XR * XCU;   // 720
}
using namespace cv;

__global__ __launch_bounds__(NT, 2)
void costvol_kernel(const float* __restrict__ x1g,
                    const float* __restrict__ x2g,
                    float* __restrict__ outg)
{
  __shared__ __align__(16) float x2s[PIPE][XR][XC];
  __shared__ __align__(16) float x1s[PIPE][HT][WT];

  const int tid = threadIdx.x;
  const int tc  = tid & 15;          // w-group: owns pixels w0+4*tc .. +3
  const int hl  = (tid >> 4) & 1;    // local h row
  const int ig  = tid >> 5;          // i-group 0..8 == warp id; i = ig - 4

  const int w0 = blockIdx.x * WT;
  const int h0 = blockIdx.y * HT;
  const int b  = blockIdx.z;

  // ---------- c-invariant staging descriptors (hoisted out of the loop) ----
  // x2 halo fill: flat idx = tid + t*NT over 720 elems (t=0,1 always; t=2 iff tid<144)
  int  s_soff[3];   // smem float offset (row*XC + col)
  int  s_goff[3];   // gmem offset within channel plane (or 0)
  bool s_val [3];
  #pragma unroll
  for (int t = 0; t < 3; t++){
    const int idx = tid + t * NT;
    const int r   = idx / XCU;
    const int cc  = idx - r * XCU;
    const int gh  = h0 - 4 + r;
    const int gw  = w0 - 4 + cc;
    const bool v  = (idx < X2ELEMS) &&
                    ((unsigned)gh < (unsigned)H) && ((unsigned)gw < (unsigned)W);
    s_soff[t] = r * XC + cc;
    s_goff[t] = v ? (gh * W + gw) : 0;
    s_val [t] = v;
  }
  const bool t2run = (tid < X2ELEMS - 2 * NT);   // tid < 144
  // x1 fill: one element per thread for tid < 128
  const bool a_run = tid < HT * WT;
  const int  a_soff = (tid >> 6) * WT + (tid & 63);
  const int  a_goff = (h0 + (tid >> 6)) * W + w0 + (tid & 63);

  const int cbase = b * C * HW;

  auto stage = [&](int c, int slot){
    const float* p2 = x2g + cbase + c * HW;
    float* d2 = &x2s[slot][0][0];
    {
      float v0 = s_val[0] ? __ldg(p2 + s_goff[0]) : 0.f;
      float v1 = s_val[1] ? __ldg(p2 + s_goff[1]) : 0.f;
      d2[s_soff[0]] = v0;
      d2[s_soff[1]] = v1;
      if (t2run){
        float v2 = s_val[2] ? __ldg(p2 + s_goff[2]) : 0.f;
        d2[s_soff[2]] = v2;
      }
    }
    if (a_run)
      (&x1s[slot][0][0])[a_soff] = __ldg(x1g + cbase + c * HW + a_goff);
  };

  // 9 j * 2 w-pairs packed accumulators (36 regs)
  ull acc[9][2];
  #pragma unroll
  for (int jj = 0; jj < 9; jj++){ acc[jj][0] = 0ull; acc[jj][1] = 0ull; }

  stage(0, 0); stage(1, 1); stage(2, 2);
  __syncthreads();

  const int rr = hl + 8 - ig;        // smem row of x2[h - i]

  for (int c = 0; c < C; c++){
    const int slot = c & (PIPE - 1);
    if (c + PIPE - 1 < C) stage(c + PIPE - 1, (c + PIPE - 1) & (PIPE - 1));

    // x1 pair constants for this channel: (w,w+1) and (w+2,w+3)
    const float4 a4 = *(const float4*)&x1s[slot][hl][tc * 4];
    const ull ap0 = pk(a4.x, a4.y);
    const ull ap1 = pk(a4.z, a4.w);

    // 12 x2 floats covering all j shifts for 4 pixels
    const float* rp = &x2s[slot][rr][tc * 4];
    const float4 b0 = *(const float4*)(rp);
    const float4 b1 = *(const float4*)(rp + 4);
    const float4 b2 = *(const float4*)(rp + 8);
    const float f[12] = {b0.x, b0.y, b0.z, b0.w,
                         b1.x, b1.y, b1.z, b1.w,
                         b2.x, b2.y, b2.z, b2.w};
    ull pr[11];
    #pragma unroll
    for (int t = 0; t < 11; t++) pr[t] = pk(f[t], f[t + 1]);

    #pragma unroll
    for (int jj = 0; jj < 9; jj++){
      acc[jj][0] = f2fma(ap0, pr[8  - jj], acc[jj][0]);
      acc[jj][1] = f2fma(ap1, pr[10 - jj], acc[jj][1]);
    }
    __syncthreads();
  }

  // ---------------- epilogue: scale by 1/81 and store ----------------
  const float invD = 1.0f / 81.0f;
  const int i = ig - 4;
  const int h = h0 + hl;
  const int w = w0 + tc * 4;
  #pragma unroll
  for (int jj = 0; jj < 9; jj++){
    const int j = jj - 4;
    const int k = (9 * i + j + 81) % 81;   // python-mod wraparound
    const float2 p0 = upk(acc[jj][0]);
    const float2 p1 = upk(acc[jj][1]);
    const float4 o = make_float4(p0.x * invD, p0.y * invD,
                                 p1.x * invD, p1.y * invD);
    *(float4*)&outg[((size_t)(b * D + k) * H + h) * W + w] = o;
  }
}

extern "C" void kernel_launch(void* const* d_in, const int* in_sizes, int n_in,
                              void* d_out, int out_size)
{
  const float* x1 = (const float*)d_in[0];
  const float* x2 = (const float*)d_in[1];
  float* out = (float*)d_out;
  dim3 grid(W / WT, H / HT, B);   // (4, 64, 4) = 1024 blocks
  costvol_kernel<<<grid, NT>>>(x1, x2, out);
}

// round 4
// speedup vs baseline: 3.1722x; 3.1722x over previous
#include <cuda_runtime.h>

typedef unsigned long long ull;

// ---- packed f32x2 helpers (Blackwell FFMA2 path: only reachable via PTX) ----
__device__ __forceinline__ ull pk(float lo, float hi){
  ull r; asm("mov.b64 %0, {%1, %2};" : "=l"(r) : "f"(lo), "f"(hi)); return r;
}
__device__ __forceinline__ float2 upk(ull v){
  float2 r; asm("mov.b64 {%0, %1}, %2;" : "=f"(r.x), "=f"(r.y) : "l"(v)); return r;
}
__device__ __forceinline__ ull f2fma(ull a, ull b, ull c){
  ull d; asm("fma.rn.f32x2 %0, %1, %2, %3;" : "=l"(d) : "l"(a), "l"(b), "l"(c)); return d;
}

// ---- cp.async (LDGSTS) helpers ----
__device__ __forceinline__ void cpa4(unsigned d, const void* g, int srcsz){
  asm volatile("cp.async.ca.shared.global [%0], [%1], 4, %2;"
               :: "r"(d), "l"(g), "r"(srcsz));
}
__device__ __forceinline__ void cpa_commit(){
  asm volatile("cp.async.commit_group;");
}
__device__ __forceinline__ void cpa_wait2(){
  asm volatile("cp.async.wait_group 2;");
}

namespace cv {
constexpr int B = 4, C = 128, H = 128, W = 256, D = 81;
constexpr int HT = 2;      // output rows per block
constexpr int WT = 64;     // output cols per block
constexpr int XR = 10;     // x2 halo rows (HT + 8)
constexpr int XCU = 72;    // x2 halo cols used (WT + 8)
constexpr int XC = 80;     // padded stride
constexpr int NT = 288;    // 16 w-groups * 2 h * 9 i  (one warp per i-value)
constexpr int PIPE = 4;    // slots
constexpr int CPB = 2;     // channels per slot
constexpr int HW = H * W;
constexpr int X2ELEMS = XR * XCU;          // 720
constexpr int SLOT2F = CPB * XR * XC;      // floats per x2 slot
constexpr int CH2F   = XR * XC;
constexpr int SLOT1F = CPB * HT * WT;
constexpr int CH1F   = HT * WT;
}
using namespace cv;

__global__ __launch_bounds__(NT, 2)
void costvol_kernel(const float* __restrict__ x1g,
                    const float* __restrict__ x2g,
                    float* __restrict__ outg)
{
  __shared__ __align__(16) float x2s[PIPE][CPB][XR][XC];  // 25.6 KB
  __shared__ __align__(16) float x1s[PIPE][CPB][HT][WT];  //  4.0 KB

  const int tid = threadIdx.x;
  const int tc  = tid & 15;          // w-group: owns pixels w0+4*tc .. +3
  const int hl  = (tid >> 4) & 1;    // local h row
  const int ig  = tid >> 5;          // warp id = i-group; i = ig - 4

  const int w0 = blockIdx.x * WT;
  const int h0 = blockIdx.y * HT;
  const int b  = blockIdx.z;

  // ---------- c-invariant staging descriptors ----------
  int s_soff[3], s_goff[3], s_sz[3];
  #pragma unroll
  for (int t = 0; t < 3; t++){
    const int idx = tid + t * NT;
    const int r   = idx / XCU;
    const int cc  = idx - r * XCU;
    const int gh  = h0 - 4 + r;
    const int gw  = w0 - 4 + cc;
    const bool v  = (idx < X2ELEMS) &&
                    ((unsigned)gh < (unsigned)H) && ((unsigned)gw < (unsigned)W);
    s_soff[t] = (r * XC + cc) * 4;
    s_goff[t] = v ? (gh * W + gw) : 0;
    s_sz [t]  = v ? 4 : 0;
  }
  const bool t2run = (tid < X2ELEMS - 2 * NT);   // tid < 144 (valid smem slot)
  const bool a_run = tid < CH1F;                 // tid < 128
  const int  a_soff = tid * 4;
  const int  a_goff = (h0 + (tid >> 6)) * W + w0 + (tid & 63);

  const int cbase = b * C * HW;
  const unsigned x2sb = (unsigned)__cvta_generic_to_shared(&x2s[0][0][0][0]);
  const unsigned x1sb = (unsigned)__cvta_generic_to_shared(&x1s[0][0][0][0]);

  auto issue_slot = [&](int slot, int c0){   // stage channels c0, c0+1
    #pragma unroll
    for (int q = 0; q < CPB; q++){
      const float* p2 = x2g + cbase + (c0 + q) * HW;
      const unsigned d2 = x2sb + (slot * SLOT2F + q * CH2F) * 4;
      cpa4(d2 + s_soff[0], p2 + s_goff[0], s_sz[0]);
      cpa4(d2 + s_soff[1], p2 + s_goff[1], s_sz[1]);
      if (t2run) cpa4(d2 + s_soff[2], p2 + s_goff[2], s_sz[2]);
      if (a_run)
        cpa4(x1sb + (slot * SLOT1F + q * CH1F) * 4 + a_soff,
             x1g + cbase + (c0 + q) * HW + a_goff, 4);
    }
    cpa_commit();
  };

  // 9 j * 2 w-pairs packed accumulators (36 regs)
  ull acc[9][2];
  #pragma unroll
  for (int jj = 0; jj < 9; jj++){ acc[jj][0] = 0ull; acc[jj][1] = 0ull; }

  issue_slot(0, 0);
  issue_slot(1, CPB);
  issue_slot(2, 2 * CPB);

  const int rr = hl + 8 - ig;        // smem row of x2[h - i]
  constexpr int NIT = C / CPB;       // 64 slot-iterations

  for (int s = 0; s < NIT; s++){
    const int slot = s & (PIPE - 1);
    cpa_wait2();                     // groups <= s complete (3+s committed)
    __syncthreads();                 // data visible; prev readers of slot s-1 done

    // issue next slot immediately (max lookahead), then compute
    const int cn = (s + PIPE - 1) * CPB;
    if (cn < C) issue_slot((s + PIPE - 1) & (PIPE - 1), cn);
    else        cpa_commit();        // keep group arithmetic uniform

    #pragma unroll
    for (int q = 0; q < CPB; q++){
      const float4 a4 = *(const float4*)&x1s[slot][q][hl][tc * 4];
      const ull ap0 = pk(a4.x, a4.y);
      const ull ap1 = pk(a4.z, a4.w);

      const float* rp = &x2s[slot][q][rr][tc * 4];
      const float4 b0 = *(const float4*)(rp);
      const float4 b1 = *(const float4*)(rp + 4);
      const float4 b2 = *(const float4*)(rp + 8);
      const float f[12] = {b0.x, b0.y, b0.z, b0.w,
                           b1.x, b1.y, b1.z, b1.w,
                           b2.x, b2.y, b2.z, b2.w};
      ull pr[11];
      #pragma unroll
      for (int t = 0; t < 11; t++) pr[t] = pk(f[t], f[t + 1]);

      #pragma unroll
      for (int jj = 0; jj < 9; jj++){
        acc[jj][0] = f2fma(ap0, pr[8  - jj], acc[jj][0]);
        acc[jj][1] = f2fma(ap1, pr[10 - jj], acc[jj][1]);
      }
    }
  }

  // ---------------- epilogue: scale by 1/81 and store ----------------
  const float invD = 1.0f / 81.0f;
  const int i = ig - 4;
  const int h = h0 + hl;
  const int w = w0 + tc * 4;
  #pragma unroll
  for (int jj = 0; jj < 9; jj++){
    const int j = jj - 4;
    const int k = (9 * i + j + 81) % 81;   // python-mod wraparound
    const float2 p0 = upk(acc[jj][0]);
    const float2 p1 = upk(acc[jj][1]);
    const float4 o = make_float4(p0.x * invD, p0.y * invD,
                                 p1.x * invD, p1.y * invD);
    *(float4*)&outg[((size_t)(b * D + k) * H + h) * W + w] = o;
  }
}

extern "C" void kernel_launch(void* const* d_in, const int* in_sizes, int n_in,
                              void* d_out, int out_size)
{
  const float* x1 = (const float*)d_in[0];
  const float* x2 = (const float*)d_in[1];
  float* out = (float*)d_out;
  dim3 grid(W / WT, H / HT, B);   // (4, 64, 4) = 1024 blocks
  costvol_kernel<<<grid, NT>>>(x1, x2, out);
}

// round 5
// speedup vs baseline: 3.4644x; 1.0921x over previous
#include <cuda_runtime.h>

typedef unsigned long long ull;

// ---- packed f32x2 helpers ----
__device__ __forceinline__ ull pk(float lo, float hi){
  ull r; asm("mov.b64 %0, {%1, %2};" : "=l"(r) : "f"(lo), "f"(hi)); return r;
}
__device__ __forceinline__ float2 upk(ull v){
  float2 r; asm("mov.b64 {%0, %1}, %2;" : "=f"(r.x), "=f"(r.y) : "l"(v)); return r;
}
__device__ __forceinline__ ull f2fma(ull a, ull b, ull c){
  ull d; asm("fma.rn.f32x2 %0, %1, %2, %3;" : "=l"(d) : "l"(a), "l"(b), "l"(c)); return d;
}

// ---- cp.async helpers (16B with zfill predicate) ----
__device__ __forceinline__ void cpa16(unsigned d, const void* g, int srcsz){
  asm volatile("cp.async.cg.shared.global [%0], [%1], 16, %2;"
               :: "r"(d), "l"(g), "r"(srcsz));
}
__device__ __forceinline__ void cpa_commit(){
  asm volatile("cp.async.commit_group;");
}
__device__ __forceinline__ void cpa_wait2(){
  asm volatile("cp.async.wait_group 2;");
}

namespace cv {
constexpr int B = 4, C = 128, H = 128, W = 256, D = 81;
constexpr int HT = 2;      // output rows per block
constexpr int WT = 64;     // output cols per block
constexpr int XR = 10;     // x2 halo rows (HT + 8)
constexpr int XCW = 96;    // widened, 16B-aligned x2 cols [w0-16, w0+80)
constexpr int XC  = 104;   // padded smem stride (floats, 16B-aligned rows)
constexpr int NT = 288;    // 16 w-groups * 2 h * 9 i (one warp per i-value)
constexpr int PIPE = 4;
constexpr int CPB = 2;     // channels per slot
constexpr int HW = H * W;
constexpr int X2CH = 240;  // x2 float4 chunks per channel (10 rows * 24)
constexpr int X1CH = 32;   // x1 float4 chunks per channel (128 floats)
constexpr int CH2F = XR * XC;      // x2 floats per channel slab (1040)
constexpr int CH1F = HT * WT;      // x1 floats per channel slab (128)
constexpr int SLOT2F = CPB * CH2F;
constexpr int SLOT1F = CPB * CH1F;
}
using namespace cv;

__global__ __launch_bounds__(NT, 2)
void costvol_kernel(const float* __restrict__ x1g,
                    const float* __restrict__ x2g,
                    float* __restrict__ outg)
{
  __shared__ __align__(16) float x2s[PIPE][CPB][XR][XC];  // 33.3 KB
  __shared__ __align__(16) float x1s[PIPE][CPB][HT][WT];  //  4.0 KB

  const int tid = threadIdx.x;
  const int tc  = tid & 15;          // w-group: pixels w0+4*tc .. +3
  const int hl  = (tid >> 4) & 1;    // local h row
  const int ig  = tid >> 5;          // warp id; i = ig - 4

  const int w0 = blockIdx.x * WT;
  const int h0 = blockIdx.y * HT;
  const int b  = blockIdx.z;

  // ---------- c-invariant staging descriptor: ONE 16B chunk per thread ------
  // tid <  240 : x2 chunk (row = tid/24, 4-col group = tid%24)
  // 240<=tid<272: x1 chunk
  // tid >= 272 : idle
  bool do2 = false, do1 = false;
  int  g_off = 0, s_off = 0, srcsz = 0;
  if (tid < X2CH){
    const int r   = tid / 24;
    const int c4  = tid - r * 24;
    const int gh  = h0 - 4 + r;
    const int gw  = w0 - 16 + 4 * c4;
    const bool v  = ((unsigned)gh < (unsigned)H) && ((unsigned)gw < (unsigned)W);
    do2   = true;
    g_off = v ? (gh * W + gw) : 0;
    srcsz = v ? 16 : 0;
    s_off = (r * XC + 4 * c4) * 4;
  } else if (tid < X2CH + X1CH){
    const int k = tid - X2CH;
    do1   = true;
    g_off = (h0 + (k >> 4)) * W + w0 + 4 * (k & 15);
    srcsz = 16;
    s_off = ((k >> 4) * WT + 4 * (k & 15)) * 4;
  }

  const int cbase = b * C * HW;
  const unsigned x2sb = (unsigned)__cvta_generic_to_shared(&x2s[0][0][0][0]);
  const unsigned x1sb = (unsigned)__cvta_generic_to_shared(&x1s[0][0][0][0]);

  auto issue_slot = [&](int slot, int c0){
    #pragma unroll
    for (int q = 0; q < CPB; q++){
      const int c = c0 + q;
      if (do2) cpa16(x2sb + (slot * SLOT2F + q * CH2F) * 4 + s_off,
                     x2g + cbase + c * HW + g_off, srcsz);
      if (do1) cpa16(x1sb + (slot * SLOT1F + q * CH1F) * 4 + s_off,
                     x1g + cbase + c * HW + g_off, 16);
    }
    cpa_commit();
  };

  // 9 j * 2 w-pairs packed accumulators (36 regs)
  ull acc[9][2];
  #pragma unroll
  for (int jj = 0; jj < 9; jj++){ acc[jj][0] = 0ull; acc[jj][1] = 0ull; }

  issue_slot(0, 0);
  issue_slot(1, CPB);
  issue_slot(2, 2 * CPB);

  const int rr = hl + 8 - ig;        // smem row of x2[h - i]
  constexpr int NIT = C / CPB;

  for (int s = 0; s < NIT; s++){
    const int slot = s & (PIPE - 1);
    cpa_wait2();
    __syncthreads();

    const int cn = (s + PIPE - 1) * CPB;
    if (cn < C) issue_slot((s + PIPE - 1) & (PIPE - 1), cn);
    else        cpa_commit();

    #pragma unroll
    for (int q = 0; q < CPB; q++){
      // x1 pairs: (w,w+1),(w+2,w+3) straight from an LDS.128 — even-aligned
      const ulonglong2 av = *(const ulonglong2*)&x1s[slot][q][hl][tc * 4];
      const ull ap0 = av.x, ap1 = av.y;

      // 12-float x2 window as 3x LDS.128 -> even pairs t=0,2,4,6,8,10 free
      const float* rp = &x2s[slot][q][rr][4 * tc + 12];
      const ulonglong2 e0 = *(const ulonglong2*)(rp);      // pr0,  pr2
      const ulonglong2 e1 = *(const ulonglong2*)(rp + 4);  // pr4,  pr6
      const ulonglong2 e2 = *(const ulonglong2*)(rp + 8);  // pr8,  pr10

      ull pr[11];
      pr[0] = e0.x; pr[2] = e0.y; pr[4] = e1.x;
      pr[6] = e1.y; pr[8] = e2.x; pr[10] = e2.y;
      // odd pairs: 2 MOVs each (cross-boundary)
      pr[1] = pk(upk(e0.x).y, upk(e0.y).x);
      pr[3] = pk(upk(e0.y).y, upk(e1.x).x);
      pr[5] = pk(upk(e1.x).y, upk(e1.y).x);
      pr[7] = pk(upk(e1.y).y, upk(e2.x).x);
      pr[9] = pk(upk(e2.x).y, upk(e2.y).x);

      #pragma unroll
      for (int jj = 0; jj < 9; jj++){
        acc[jj][0] = f2fma(ap0, pr[8  - jj], acc[jj][0]);
        acc[jj][1] = f2fma(ap1, pr[10 - jj], acc[jj][1]);
      }
    }
  }

  // ---------------- epilogue: scale by 1/81 and store ----------------
  const float invD = 1.0f / 81.0f;
  const int i = ig - 4;
  const int h = h0 + hl;
  const int w = w0 + tc * 4;
  #pragma unroll
  for (int jj = 0; jj < 9; jj++){
    const int j = jj - 4;
    const int k = (9 * i + j + 81) % 81;   // python-mod wraparound
    const float2 p0 = upk(acc[jj][0]);
    const float2 p1 = upk(acc[jj][1]);
    const float4 o = make_float4(p0.x * invD, p0.y * invD,
                                 p1.x * invD, p1.y * invD);
    *(float4*)&outg[((size_t)(b * D + k) * H + h) * W + w] = o;
  }
}

extern "C" void kernel_launch(void* const* d_in, const int* in_sizes, int n_in,
                              void* d_out, int out_size)
{
  const float* x1 = (const float*)d_in[0];
  const float* x2 = (const float*)d_in[1];
  float* out = (float*)d_out;
  dim3 grid(W / WT, H / HT, B);   // (4, 64, 4) = 1024 blocks
  costvol_kernel<<<grid, NT>>>(x1, x2, out);
}

// round 8
// speedup vs baseline: 4.4261x; 1.2776x over previous
#include <cuda_runtime.h>

typedef unsigned long long ull;

// ---- packed f32x2 helpers ----
__device__ __forceinline__ ull pk(float lo, float hi){
  ull r; asm("mov.b64 %0, {%1, %2};" : "=l"(r) : "f"(lo), "f"(hi)); return r;
}
__device__ __forceinline__ float2 upk(ull v){
  float2 r; asm("mov.b64 {%0, %1}, %2;" : "=f"(r.x), "=f"(r.y) : "l"(v)); return r;
}
__device__ __forceinline__ ull f2fma(ull a, ull b, ull c){
  ull d; asm("fma.rn.f32x2 %0, %1, %2, %3;" : "=l"(d) : "l"(a), "l"(b), "l"(c)); return d;
}

// ---- cp.async helpers ----
__device__ __forceinline__ void cpa16(unsigned d, const float* g, int srcsz){
  asm volatile("cp.async.cg.shared.global [%0], [%1], 16, %2;"
               :: "r"(d), "l"(g), "r"(srcsz));
}
__device__ __forceinline__ void cpa_commit(){
  asm volatile("cp.async.commit_group;");
}
template<int N> __device__ __forceinline__ void cpa_waitg(){
  asm volatile("cp.async.wait_group %0;" :: "n"(N));
}

namespace cv {
constexpr int B = 4, C = 128, H = 128, W = 256, D = 81;
constexpr int HT = 2;      // output rows per block
constexpr int WT = 64;     // output cols per block
constexpr int XR = 10;     // x2 halo rows
constexpr int XC = 104;    // x2 smem row stride (floats); cols cover [w0-16,w0+80)
constexpr int NT = 288;    // 16 w-groups * 2 h * 9 i
constexpr int PIPE = 4;
constexpr int CPB = 2;     // channels per slot
constexpr int HW = H * W;
constexpr int CH2F = XR * XC;        // 1040
constexpr int CH1F = HT * WT;        // 128
constexpr int SLOT2F = CPB * CH2F;   // 2080
constexpr int SLOT1F = CPB * CH1F;   // 256
}
using namespace cv;

__global__ __launch_bounds__(NT, 2)
void costvol_kernel(const float* __restrict__ x1g,
                    const float* __restrict__ x2g,
                    float* __restrict__ outg)
{
  __shared__ __align__(16) float x2s[PIPE][CPB][XR][XC];  // 33.3 KB
  __shared__ __align__(16) float x1s[PIPE][CPB][HT][WT];  //  4.0 KB
  __shared__ __align__(16) float dummy16[4];

  const int tid = threadIdx.x;
  const int tc  = tid & 15;          // w-group: pixels w0+4*tc .. +3
  const int hl  = (tid >> 4) & 1;    // local h row
  const int ig  = tid >> 5;          // warp id; i = ig - 4

  const int w0 = blockIdx.x * WT;
  const int h0 = blockIdx.y * HT;
  const int b  = blockIdx.z;
  const int cbase = b * C * HW;

  // ---------- uniform one-chunk-per-thread staging descriptor ----------
  // tid<240: x2 chunk; 240..271: x1 chunk; else dummy
  unsigned sb; int szcp; unsigned qstr, slstr; const float* gp;
  if (tid < 240){
    const int r  = tid / 24;
    const int c4 = tid - r * 24;
    const int gh = h0 - 4 + r;
    const int gw = w0 - 16 + 4 * c4;
    const bool v = ((unsigned)gh < (unsigned)H) && ((unsigned)gw < (unsigned)W);
    sb    = (unsigned)__cvta_generic_to_shared(&x2s[0][0][r][4 * c4]);
    szcp  = v ? 16 : 0;
    qstr  = CH2F * 4;  slstr = SLOT2F * 4;
    gp    = x2g + cbase + (v ? (gh * W + gw) : 0);
  } else if (tid < 272){
    const int k = tid - 240;
    sb    = (unsigned)__cvta_generic_to_shared(&x1s[0][0][k >> 4][4 * (k & 15)]);
    szcp  = 16;
    qstr  = CH1F * 4;  slstr = SLOT1F * 4;
    gp    = x1g + cbase + (h0 + (k >> 4)) * W + w0 + 4 * (k & 15);
  } else {
    sb    = (unsigned)__cvta_generic_to_shared(&dummy16[0]);
    szcp  = 0;  qstr = 0;  slstr = 0;
    gp    = x2g;
  }
  const unsigned sa0 = sb, sa1 = sb + slstr, sa2 = sb + 2*slstr, sa3 = sb + 3*slstr;

#define ISSUE(SA) do{ cpa16((SA), gp, szcp); cpa16((SA) + qstr, gp + HW, szcp); \
                      cpa_commit(); gp += 2 * HW; }while(0)

  // fixed per-thread smem read bases (compile-time slot offsets added in COMP)
  const float* x1c = &x1s[0][0][hl][4 * tc];
  const float* x2c = &x2s[0][0][hl + 8 - ig][4 * tc + 12];

  // 9 j * 2 w-pairs packed accumulators
  ull acc[9][2];
  #pragma unroll
  for (int jj = 0; jj < 9; jj++){ acc[jj][0] = 0ull; acc[jj][1] = 0ull; }

#define COMP(S) do{ \
  _Pragma("unroll") \
  for (int q = 0; q < CPB; q++){ \
    const ulonglong2 av = *(const ulonglong2*)(x1c + (S) * SLOT1F + q * CH1F); \
    const ull ap0 = av.x, ap1 = av.y; \
    const float* rp = x2c + (S) * SLOT2F + q * CH2F; \
    const ulonglong2 e0 = *(const ulonglong2*)(rp); \
    const ulonglong2 e1 = *(const ulonglong2*)(rp + 4); \
    const ulonglong2 e2 = *(const ulonglong2*)(rp + 8); \
    ull pr[11]; \
    pr[0] = e0.x; pr[2] = e0.y; pr[4] = e1.x; \
    pr[6] = e1.y; pr[8] = e2.x; pr[10] = e2.y; \
    pr[1] = pk(upk(e0.x).y, upk(e0.y).x); \
    pr[3] = pk(upk(e0.y).y, upk(e1.x).x); \
    pr[5] = pk(upk(e1.x).y, upk(e1.y).x); \
    pr[7] = pk(upk(e1.y).y, upk(e2.x).x); \
    pr[9] = pk(upk(e2.x).y, upk(e2.y).x); \
    _Pragma("unroll") \
    for (int jj = 0; jj < 9; jj++){ \
      acc[jj][0] = f2fma(ap0, pr[8  - jj], acc[jj][0]); \
      acc[jj][1] = f2fma(ap1, pr[10 - jj], acc[jj][1]); \
    } \
  } }while(0)

  // ---------------- software pipeline: 64 slot-iterations ----------------
  ISSUE(sa0); ISSUE(sa1); ISSUE(sa2);          // blocks 0,1,2 -> slots 0,1,2

  #pragma unroll 1
  for (int o = 0; o < 15; o++){
    cpa_waitg<2>(); __syncthreads(); ISSUE(sa3); COMP(0);
    cpa_waitg<2>(); __syncthreads(); ISSUE(sa0); COMP(1);
    cpa_waitg<2>(); __syncthreads(); ISSUE(sa1); COMP(2);
    cpa_waitg<2>(); __syncthreads(); ISSUE(sa2); COMP(3);
  }
  cpa_waitg<2>(); __syncthreads(); ISSUE(sa3); COMP(0);   // k=60 issues block 63
  cpa_waitg<2>(); __syncthreads();             COMP(1);
  cpa_waitg<1>(); __syncthreads();             COMP(2);
  cpa_waitg<0>(); __syncthreads();             COMP(3);

#undef ISSUE
#undef COMP

  // ---------------- epilogue: scale by 1/81 and store ----------------
  const float invD = 1.0f / 81.0f;
  const int i = ig - 4;
  const int h = h0 + hl;
  const int w = w0 + 4 * tc;
  #pragma unroll
  for (int jj = 0; jj < 9; jj++){
    const int j = jj - 4;
    const int k = (9 * i + j + 81) % 81;   // python-mod wraparound
    const float2 p0 = upk(acc[jj][0]);
    const float2 p1 = upk(acc[jj][1]);
    const float4 o = make_float4(p0.x * invD, p0.y * invD,
                                 p1.x * invD, p1.y * invD);
    *(float4*)&outg[((size_t)(b * D + k) * H + h) * W + w] = o;
  }
}

extern "C" void kernel_launch(void* const* d_in, const int* in_sizes, int n_in,
                              void* d_out, int out_size)
{
  const float* x1 = (const float*)d_in[0];
  const float* x2 = (const float*)d_in[1];
  float* out = (float*)d_out;
  dim3 grid(W / WT, H / HT, B);   // (4, 64, 4) = 1024 blocks
  costvol_kernel<<<grid, NT>>>(x1, x2, out);
}